// round 11
// baseline (speedup 1.0000x reference)
#include <cuda_runtime.h>
#include <cstdint>

// 3-level db4 wavedec (periodization) along axis 1 of (64, 4096, 64) fp32.
// Output rows: [cA3 (512) | cD3 (512) | cD2 (1024) | cD1 (2048)] x 64 feats.
//
// R11: 8-output chunks per group at every level, processed as two batched
// sub-windows (rows 0..13, then 14..21 with a 6-row register carry).
// Cuts read redundancy from 3.5 to 2.75 rows/output (-13% total L1 bytes)
// while keeping batched-MLP loads, packed f32x2 FMA, and 128-bit memory ops.

#define NTHREADS 256
#define A1_ROWS  82
#define A2_ROWS  38
#define A1_CAP   86   // level-2 chunk B reads up to row 85 (garbage rows OK)
#define A2_CAP   40

__device__ __forceinline__ void fma2(unsigned long long& acc,
                                     unsigned long long w,
                                     unsigned long long c) {
    asm("fma.rn.f32x2 %0, %1, %2, %0;" : "+l"(acc) : "l"(w), "l"(c));
}

__device__ __forceinline__ unsigned long long pneg(unsigned long long v) {
    return v ^ 0x8000000080000000ull;
}

// consume 14-row window V into 4-row accumulators:
// a[q] += V[2q+t]*RLO[t];  d[q] += s(t)*V[2q+t]*RLO[7-t]
#define CONSUME_WINDOW(V)                                           \
    _Pragma("unroll")                                               \
    for (int t = 0; t < 14; ++t) {                                  \
        const unsigned long long WL = (V)[t].x, WH = (V)[t].y;      \
        const unsigned long long nWL = (t & 1) ? pneg(WL) : WL;     \
        const unsigned long long nWH = (t & 1) ? pneg(WH) : WH;     \
        _Pragma("unroll")                                           \
        for (int q = 0; q < 4; ++q) {                               \
            const int tt = t - 2 * q;                               \
            if (tt >= 0 && tt < 8) {                                \
                fma2(aL[q], WL, clo[tt]);                           \
                fma2(aH[q], WH, clo[tt]);                           \
                fma2(dL[q], nWL, clo[7 - tt]);                      \
                fma2(dH[q], nWH, clo[7 - tt]);                      \
            }                                                       \
        }                                                           \
    }

#define ZERO_ACC                                                    \
    unsigned long long aL[4] = {}, aH[4] = {}, dL[4] = {}, dH[4] = {};

__global__ void __launch_bounds__(NTHREADS, 3)
wavedec_kernel(const float* __restrict__ x, float* __restrict__ out) {
    __shared__ ulonglong2 s_a1[A1_CAP * 16];
    __shared__ ulonglong2 s_a2[A2_CAP * 16];

    const int tid  = threadIdx.x;
    const int f4   = tid & 15;    // float4 feature lane (64 floats = 16 float4)
    const int grp  = tid >> 4;    // 0..15
    const int tile = blockIdx.x;  // 0..31
    const int b    = blockIdx.y;  // 0..63

    // Reversed approx filter: out_a[i] = sum_t src[2i+t] * RLO[t]
    const float RLO[8] = {
         0.23037781330885523f,  0.7148465705525415f,   0.6308807679295904f,
        -0.02798376941698385f, -0.18703481171888114f,  0.030841381835986965f,
         0.032883011666982945f, -0.010597401784997278f };

    unsigned long long clo[8];
#pragma unroll
    for (int t = 0; t < 8; ++t)
        clo[t] = (unsigned long long)__float_as_uint(RLO[t]) * 0x100000001ull;

    const ulonglong2* __restrict__ xb4 =
        reinterpret_cast<const ulonglong2*>(x + (size_t)b * 4096 * 64);
    ulonglong2* __restrict__ ob4 =
        reinterpret_cast<ulonglong2*>(out + (size_t)b * 4096 * 64);

    const int g0 = 128 * tile - 42;  // global x row of local window origin

    // ---- Level 1: x (global) -> cA1 (smem) + cD1 (global) ----
    // groups 0..10, 8 outputs each (group 10: rows 80..83, 82..83 discarded)
    if (grp <= 10) {
        const int i0 = grp * 8;
        const int r0 = g0 + 2 * i0;

        ulonglong2 v[14];
        if (r0 >= 0 && r0 <= 4096 - 14) {
            const ulonglong2* p = xb4 + (size_t)r0 * 16 + f4;
#pragma unroll
            for (int t = 0; t < 14; ++t)
                v[t] = p[t * 16];
        } else {
#pragma unroll
            for (int t = 0; t < 14; ++t) {
                const int r = (r0 + t + 4096) & 4095;
                v[t] = xb4[(size_t)r * 16 + f4];
            }
        }
        {
            ZERO_ACC
            CONSUME_WINDOW(v)
#pragma unroll
            for (int q = 0; q < 4; ++q) {
                const int i = i0 + q;                     // max 83 < A1_CAP
                s_a1[i * 16 + f4] = make_ulonglong2(aL[q], aH[q]);
                if (i >= 18 && i < A1_ROWS)
                    ob4[(size_t)(2048 + 64 * tile + (i - 18)) * 16 + f4] =
                        make_ulonglong2(dL[q], dH[q]);
            }
        }
        if (i0 + 4 < A1_ROWS) {                           // group 10 skips B
            ulonglong2 w[8];
            const int rW = r0 + 14;
            if (rW >= 0 && rW <= 4096 - 8) {
                const ulonglong2* p = xb4 + (size_t)rW * 16 + f4;
#pragma unroll
                for (int t = 0; t < 8; ++t)
                    w[t] = p[t * 16];
            } else {
#pragma unroll
                for (int t = 0; t < 8; ++t) {
                    const int r = (rW + t + 4096) & 4095;
                    w[t] = xb4[(size_t)r * 16 + f4];
                }
            }
            ulonglong2 v2[14];
#pragma unroll
            for (int t = 0; t < 6; ++t) v2[t] = v[8 + t];
#pragma unroll
            for (int t = 0; t < 8; ++t) v2[6 + t] = w[t];
            ZERO_ACC
            CONSUME_WINDOW(v2)
#pragma unroll
            for (int q = 0; q < 4; ++q) {
                const int i = i0 + 4 + q;                 // max 79
                s_a1[i * 16 + f4] = make_ulonglong2(aL[q], aH[q]);
                if (i >= 18 && i < A1_ROWS)
                    ob4[(size_t)(2048 + 64 * tile + (i - 18)) * 16 + f4] =
                        make_ulonglong2(dL[q], dH[q]);
            }
        }
    }
    __syncthreads();

    // ---- Level 2: cA1 (smem) -> cA2 (smem) + cD2 (global) ----
    // groups 0..4, 8 outputs each (group 4: 32..39, 38..39 discarded)
    if (grp <= 4) {
        const int i0 = grp * 8;
        const ulonglong2* p = s_a1 + (size_t)(2 * i0) * 16 + f4;

        ulonglong2 v[14];
#pragma unroll
        for (int t = 0; t < 14; ++t)
            v[t] = p[t * 16];
        {
            ZERO_ACC
            CONSUME_WINDOW(v)
#pragma unroll
            for (int q = 0; q < 4; ++q) {
                const int i = i0 + q;                     // max 35
                s_a2[i * 16 + f4] = make_ulonglong2(aL[q], aH[q]);
                if (i >= 6 && i < A2_ROWS)
                    ob4[(size_t)(1024 + 32 * tile + (i - 6)) * 16 + f4] =
                        make_ulonglong2(dL[q], dH[q]);
            }
        }
        {
            ulonglong2 w[8];
#pragma unroll
            for (int t = 0; t < 8; ++t)
                w[t] = p[(14 + t) * 16];                  // rows 2i0+14..2i0+21 <= 85
            ulonglong2 v2[14];
#pragma unroll
            for (int t = 0; t < 6; ++t) v2[t] = v[8 + t];
#pragma unroll
            for (int t = 0; t < 8; ++t) v2[6 + t] = w[t];
            ZERO_ACC
            CONSUME_WINDOW(v2)
#pragma unroll
            for (int q = 0; q < 4; ++q) {
                const int i = i0 + 4 + q;                 // max 39 < A2_CAP
                s_a2[i * 16 + f4] = make_ulonglong2(aL[q], aH[q]);
                if (i >= 6 && i < A2_ROWS)
                    ob4[(size_t)(1024 + 32 * tile + (i - 6)) * 16 + f4] =
                        make_ulonglong2(dL[q], dH[q]);
            }
        }
    }
    __syncthreads();

    // ---- Level 3: cA2 (smem) -> cA3 + cD3 (global) ----
    // groups 0..1, 8 outputs each
    if (grp <= 1) {
        const int i0 = grp * 8;
        const ulonglong2* p = s_a2 + (size_t)(2 * i0) * 16 + f4;

        ulonglong2 v[14];
#pragma unroll
        for (int t = 0; t < 14; ++t)
            v[t] = p[t * 16];
        {
            ZERO_ACC
            CONSUME_WINDOW(v)
#pragma unroll
            for (int q = 0; q < 4; ++q) {
                const int i = i0 + q;
                ob4[(size_t)(16 * tile + i) * 16 + f4] =
                    make_ulonglong2(aL[q], aH[q]);
                ob4[(size_t)(512 + 16 * tile + i) * 16 + f4] =
                    make_ulonglong2(dL[q], dH[q]);
            }
        }
        {
            ulonglong2 w[8];
#pragma unroll
            for (int t = 0; t < 8; ++t)
                w[t] = p[(14 + t) * 16];                  // rows <= 37
            ulonglong2 v2[14];
#pragma unroll
            for (int t = 0; t < 6; ++t) v2[t] = v[8 + t];
#pragma unroll
            for (int t = 0; t < 8; ++t) v2[6 + t] = w[t];
            ZERO_ACC
            CONSUME_WINDOW(v2)
#pragma unroll
            for (int q = 0; q < 4; ++q) {
                const int i = i0 + 4 + q;
                ob4[(size_t)(16 * tile + i) * 16 + f4] =
                    make_ulonglong2(aL[q], aH[q]);
                ob4[(size_t)(512 + 16 * tile + i) * 16 + f4] =
                    make_ulonglong2(dL[q], dH[q]);
            }
        }
    }
}

extern "C" void kernel_launch(void* const* d_in, const int* in_sizes, int n_in,
                              void* d_out, int out_size) {
    const float* x = (const float*)d_in[0];
    float* out = (float*)d_out;
    dim3 grid(32, 64);
    wavedec_kernel<<<grid, NTHREADS>>>(x, out);
}